// round 5
// baseline (speedup 1.0000x reference)
#include <cuda_runtime.h>

// ---------------- problem constants (fixed by the dataset) ----------------
#define NA 8      // agents
#define BB 32     // batch per agent
#define NB 256    // NA*BB
#define FF 256    // features
#define TT 64     // seq (token axis)
#define HH 8      // heads
#define DD 32     // head dim
#define SCALE 0.0625f  // 1/sqrt(FF)

// ---------------- scratch (device globals; no allocations allowed) --------
__device__ float g_q[HH*NA*BB*TT*DD];   // [h][n][b][t][d]
__device__ float g_k[HH*NA*BB*TT*DD];
__device__ float g_v[HH*NA*BB*TT*DD];
__device__ float g_y[NB*FF*TT];         // [nb][f][t], f = h*32+d

// ---------------- packed fp32x2 helpers (Blackwell FFMA2) -----------------
typedef unsigned long long u64;

__device__ __forceinline__ u64 dup2(float x) {
    u64 r;
    asm("mov.b64 %0, {%1, %1};" : "=l"(r) : "f"(x));
    return r;
}
__device__ __forceinline__ void unpack2(u64 v, float& lo, float& hi) {
    asm("mov.b64 {%0, %1}, %2;" : "=f"(lo), "=f"(hi) : "l"(v));
}
__device__ __forceinline__ u64 fma2(u64 a, u64 b, u64 c) {
    u64 d;
    asm("fma.rn.f32x2 %0, %1, %2, %3;" : "=l"(d) : "l"(a), "l"(b), "l"(c));
    return d;
}
// 16B shared load straight into two packed-f32x2 registers
__device__ __forceinline__ void lds_v2u64(const float* p, u64& a, u64& b) {
    u64 addr = (u64)__cvta_generic_to_shared(p);
    asm("ld.shared.v2.u64 {%0, %1}, [%2];" : "=l"(a), "=l"(b) : "l"(addr));
}

// ======================== kernel 1: QKV projections ========================
// grid = 768 (mat*256 + nb), block = 256.
// out[h][n][b][t][d] = sum_f x[nb][f][t] * W[h][f][d]
// Thread (fg = tid&31, tg = tid>>5): outputs fout = fg + 32k (k = head),
// t = tg*8 .. tg*8+7.  8 fout x 8 t = 64 outputs (32 u64 accs).
__global__ void __launch_bounds__(256, 2) qkv_kernel(
    const float* __restrict__ x,
    const float* __restrict__ Wq,
    const float* __restrict__ Wk,
    const float* __restrict__ Wv)
{
    __shared__ __align__(16) float xs[32 * 64];     // [fl][t]   8 KB
    __shared__ __align__(16) float ws[32 * 257];    // [fl][fout], 257-pad  32.1 KB

    const int bid = blockIdx.x;
    const int nb  = bid & 255;
    const int mat = bid >> 8;            // 0=q, 1=k, 2=v
    const float* W  = (mat == 0) ? Wq : (mat == 1) ? Wk : Wv;
    float* outg     = (mat == 0) ? g_q : (mat == 1) ? g_k : g_v;

    const int tid = threadIdx.x;
    const int fg  = tid & 31;
    const int tg  = tid >> 5;
    const int t0  = tg * 8;

    u64 acc[8][4];
    #pragma unroll
    for (int k = 0; k < 8; k++)
        #pragma unroll
        for (int p = 0; p < 4; p++) acc[k][p] = 0ull;

    const float* xb = x + (size_t)nb * (FF * TT);

    for (int c = 0; c < 8; c++) {
        const int f0 = c * 32;
        __syncthreads();
        {   // stage x chunk: rows f0..f0+31, contiguous 2048 floats
            const float4* s4 = (const float4*)(xb + f0 * TT);
            float4* d4 = (float4*)xs;
            d4[tid]       = s4[tid];
            d4[tid + 256] = s4[tid + 256];
        }
        {   // stage W chunk into ws[fl][h*32+d] with 257-pad rows
            #pragma unroll
            for (int m = 0; m < 8; m++) {
                int jj = tid + m * 256;            // 0..2047 (float4 index)
                int h  = jj >> 8;
                int r  = jj & 255;                 // float4 idx within h block
                int fl = r >> 3;
                int d0 = (r & 7) * 4;
                float4 wv = ((const float4*)(W + h * (FF * DD) + f0 * DD))[r];
                float* dst = ws + fl * 257 + h * 32 + d0;
                dst[0] = wv.x; dst[1] = wv.y; dst[2] = wv.z; dst[3] = wv.w;
            }
        }
        __syncthreads();

        #pragma unroll 2
        for (int fl = 0; fl < 32; fl++) {
            u64 xp[4];
            lds_v2u64(xs + fl * 64 + t0, xp[0], xp[1]);
            lds_v2u64(xs + fl * 64 + t0 + 4, xp[2], xp[3]);
            const float* wrow = ws + fl * 257 + fg;
            #pragma unroll
            for (int k = 0; k < 8; k++) {
                u64 wd = dup2(wrow[k * 32]);
                acc[k][0] = fma2(xp[0], wd, acc[k][0]);
                acc[k][1] = fma2(xp[1], wd, acc[k][1]);
                acc[k][2] = fma2(xp[2], wd, acc[k][2]);
                acc[k][3] = fma2(xp[3], wd, acc[k][3]);
            }
        }
    }

    // write: [h][n][b][t][d], h = k, d = fg; coalesced (lanes span d)
    const int n = nb >> 5, b = nb & 31;
    #pragma unroll
    for (int k = 0; k < 8; k++) {
        float* o = outg + (size_t)(((k * NA + n) * BB + b) * TT) * DD + fg;
        #pragma unroll
        for (int p = 0; p < 4; p++) {
            float a, bv; unpack2(acc[k][p], a, bv);
            o[(t0 + 2 * p)     * DD] = a;
            o[(t0 + 2 * p + 1) * DD] = bv;
        }
    }
}

// ======================== kernel 2: all-pairs attention ====================
// grid = 2048 (h*256 + j*32 + b), block = 256.
// q in smem (scaled); k/v prefetched to regs for i+1 during compute of i.
__global__ void __launch_bounds__(256, 2) attn_kernel()
{
    __shared__ __align__(16) float kT[DD * 66];    // [d][s], pad 66   8.4 KB
    __shared__ __align__(16) float vs[TT * DD];    // [s][d]           8 KB
    __shared__ __align__(16) float Ps[TT * 66];    // [t][s], pad 66  16.9 KB
    __shared__ __align__(16) float qs[TT * 33];    // [t][d], pad 33   8.4 KB

    const int bid = blockIdx.x;
    const int b = bid & 31, j = (bid >> 5) & 7, h = bid >> 8;
    const int tid = threadIdx.x;
    const int t0  = tid >> 3;       // rows t0 and t0+32
    const int c8  = tid & 7;        // 8-way column split

    // stage q (pre-scaled) into smem
    {
        const float* qb = g_q + (size_t)(((h * NA + j) * BB + b) * TT) * DD;
        #pragma unroll
        for (int r = 0; r < 8; r++) {
            int idx = tid + r * 256;
            int t = idx >> 5, d = idx & 31;
            qs[t * 33 + d] = qb[idx] * SCALE;
        }
    }

    u64 outA[2] = {0ull, 0ull}, outB[2] = {0ull, 0ull};

    const size_t kvstride4 = (size_t)BB * TT * DD / 4;   // float4 stride per i
    const float4* kb4 = (const float4*)(g_k + (size_t)((h * NA) * BB + b) * TT * DD);
    const float4* vb4 = (const float4*)(g_v + (size_t)((h * NA) * BB + b) * TT * DD);

    // prefetch i = 0
    float4 k4[2], v4[2];
    k4[0] = kb4[tid]; k4[1] = kb4[tid + 256];
    v4[0] = vb4[tid]; v4[1] = vb4[tid + 256];

    for (int i = 0; i < NA; i++) {
        __syncthreads();   // previous compute done -> buffers free; qs visible path
        {   // store staged k (transposed) and v
            #pragma unroll
            for (int m = 0; m < 2; m++) {
                int jj = tid + m * 256;
                int s = jj >> 3, d0 = (jj & 7) * 4;
                float4 kv = k4[m];
                kT[(d0 + 0) * 66 + s] = kv.x;
                kT[(d0 + 1) * 66 + s] = kv.y;
                kT[(d0 + 2) * 66 + s] = kv.z;
                kT[(d0 + 3) * 66 + s] = kv.w;
                ((float4*)vs)[jj] = v4[m];
            }
        }
        __syncthreads();

        if (i < NA - 1) {   // prefetch next i; latency hidden by compute below
            const float4* nk = kb4 + (size_t)(i + 1) * kvstride4;
            const float4* nv = vb4 + (size_t)(i + 1) * kvstride4;
            k4[0] = nk[tid]; k4[1] = nk[tid + 256];
            v4[0] = nv[tid]; v4[1] = nv[tid + 256];
        }

        // ---- S = q @ k^T : 4 s-pairs per row, rows t0 and t0+32 ----
        u64 sA[4] = {0ull,0ull,0ull,0ull}, sB[4] = {0ull,0ull,0ull,0ull};
        #pragma unroll 8
        for (int d = 0; d < DD; d++) {
            const u64* kr = (const u64*)(kT + d * 66);
            u64 k0 = kr[c8], k1 = kr[c8 + 8], k2 = kr[c8 + 16], k3 = kr[c8 + 24];
            u64 qda = dup2(qs[t0 * 33 + d]);
            u64 qdb = dup2(qs[(t0 + 32) * 33 + d]);
            sA[0] = fma2(k0, qda, sA[0]); sA[1] = fma2(k1, qda, sA[1]);
            sA[2] = fma2(k2, qda, sA[2]); sA[3] = fma2(k3, qda, sA[3]);
            sB[0] = fma2(k0, qdb, sB[0]); sB[1] = fma2(k1, qdb, sB[1]);
            sB[2] = fma2(k2, qdb, sB[2]); sB[3] = fma2(k3, qdb, sB[3]);
        }

        // ---- softmax over s (per key agent i) ----
        float eA[8], eB[8];
        #pragma unroll
        for (int m = 0; m < 4; m++) {
            unpack2(sA[m], eA[2*m], eA[2*m+1]);
            unpack2(sB[m], eB[2*m], eB[2*m+1]);
        }
        float mA = eA[0], mB = eB[0];
        #pragma unroll
        for (int p = 1; p < 8; p++) { mA = fmaxf(mA, eA[p]); mB = fmaxf(mB, eB[p]); }
        #pragma unroll
        for (int w = 1; w < 8; w <<= 1) {
            mA = fmaxf(mA, __shfl_xor_sync(0xffffffffu, mA, w));
            mB = fmaxf(mB, __shfl_xor_sync(0xffffffffu, mB, w));
        }
        float sumA = 0.f, sumB = 0.f;
        #pragma unroll
        for (int p = 0; p < 8; p++) {
            eA[p] = __expf(eA[p] - mA); sumA += eA[p];
            eB[p] = __expf(eB[p] - mB); sumB += eB[p];
        }
        #pragma unroll
        for (int w = 1; w < 8; w <<= 1) {
            sumA += __shfl_xor_sync(0xffffffffu, sumA, w);
            sumB += __shfl_xor_sync(0xffffffffu, sumB, w);
        }
        float invA = __frcp_rn(sumA), invB = __frcp_rn(sumB);

        float* Pa = Ps + t0 * 66;
        float* Pb = Ps + (t0 + 32) * 66;
        #pragma unroll
        for (int m = 0; m < 4; m++) {
            ((float2*)Pa)[c8 + 8*m] = make_float2(eA[2*m] * invA, eA[2*m+1] * invA);
            ((float2*)Pb)[c8 + 8*m] = make_float2(eB[2*m] * invB, eB[2*m+1] * invB);
        }
        __syncwarp();   // P rows are warp-local

        // ---- out += P @ V : this thread owns d = 4*c8 .. 4*c8+3 ----
        #pragma unroll 4
        for (int s2 = 0; s2 < 32; s2++) {
            float2 pA = ((const float2*)Pa)[s2];
            float2 pB = ((const float2*)Pb)[s2];
            u64 va0, va1, vb0, vb1;
            lds_v2u64(vs + (2 * s2)     * DD + 4 * c8, va0, va1);
            lds_v2u64(vs + (2 * s2 + 1) * DD + 4 * c8, vb0, vb1);
            u64 pA0 = dup2(pA.x), pA1 = dup2(pA.y);
            u64 pB0 = dup2(pB.x), pB1 = dup2(pB.y);
            outA[0] = fma2(va0, pA0, outA[0]); outA[1] = fma2(va1, pA0, outA[1]);
            outA[0] = fma2(vb0, pA1, outA[0]); outA[1] = fma2(vb1, pA1, outA[1]);
            outB[0] = fma2(va0, pB0, outB[0]); outB[1] = fma2(va1, pB0, outB[1]);
            outB[0] = fma2(vb0, pB1, outB[0]); outB[1] = fma2(vb1, pB1, outB[1]);
        }
        __syncwarp();
    }

    // write y[nb][h*32+d][t]
    const int nb = j * BB + b;
    float* yo = g_y + (size_t)(nb * FF + h * DD + 4 * c8) * TT + t0;
    float x0, x1, x2, x3;
    unpack2(outA[0], x0, x1); unpack2(outA[1], x2, x3);
    yo[0] = x0; yo[TT] = x1; yo[2*TT] = x2; yo[3*TT] = x3;
    unpack2(outB[0], x0, x1); unpack2(outB[1], x2, x3);
    float* yo2 = yo + 32;
    yo2[0] = x0; yo2[TT] = x1; yo2[2*TT] = x2; yo2[3*TT] = x3;
}

// ======================== kernel 3: output projection ======================
// grid = 256 (nb), block = 256.
// out[nb][g][t] = sum_f y[nb][f][t] * Wp[g][f] + bp[g]
// Thread (fg, tg): g = fg + 32k, t = tg*8..tg*8+7.
__global__ void __launch_bounds__(256, 2) proj_kernel(
    const float* __restrict__ Wp,
    const float* __restrict__ bp,
    float* __restrict__ out)
{
    __shared__ __align__(16) float ys[32 * 64];     // [fl][t]
    __shared__ __align__(16) float ws[32 * 257];    // [fl][g], 257-pad

    const int nb  = blockIdx.x;
    const int tid = threadIdx.x;
    const int fg  = tid & 31;
    const int tg  = tid >> 5;
    const int t0  = tg * 8;

    u64 acc[8][4];
    #pragma unroll
    for (int k = 0; k < 8; k++)
        #pragma unroll
        for (int p = 0; p < 4; p++) acc[k][p] = 0ull;

    const float* yb = g_y + (size_t)nb * (FF * TT);

    for (int c = 0; c < 8; c++) {
        const int f0 = c * 32;
        __syncthreads();
        {   // stage y chunk (contiguous)
            const float4* s4 = (const float4*)(yb + f0 * TT);
            float4* d4 = (float4*)ys;
            d4[tid]       = s4[tid];
            d4[tid + 256] = s4[tid + 256];
        }
        {   // stage Wp chunk transposed: ws[fl][g] = Wp[g][f0+fl]
            #pragma unroll
            for (int m = 0; m < 8; m++) {
                int jj = tid + m * 256;           // float4 index, 0..2047
                int g   = jj >> 3;
                int fl0 = (jj & 7) * 4;
                float4 wv = ((const float4*)(Wp + g * FF + f0))[jj & 7];
                ws[(fl0 + 0) * 257 + g] = wv.x;
                ws[(fl0 + 1) * 257 + g] = wv.y;
                ws[(fl0 + 2) * 257 + g] = wv.z;
                ws[(fl0 + 3) * 257 + g] = wv.w;
            }
        }
        __syncthreads();

        #pragma unroll 2
        for (int fl = 0; fl < 32; fl++) {
            u64 xp[4];
            lds_v2u64(ys + fl * 64 + t0, xp[0], xp[1]);
            lds_v2u64(ys + fl * 64 + t0 + 4, xp[2], xp[3]);
            const float* wrow = ws + fl * 257 + fg;
            #pragma unroll
            for (int k = 0; k < 8; k++) {
                u64 wd = dup2(wrow[k * 32]);
                acc[k][0] = fma2(xp[0], wd, acc[k][0]);
                acc[k][1] = fma2(xp[1], wd, acc[k][1]);
                acc[k][2] = fma2(xp[2], wd, acc[k][2]);
                acc[k][3] = fma2(xp[3], wd, acc[k][3]);
            }
        }
    }

    #pragma unroll
    for (int k = 0; k < 8; k++) {
        const int g = fg + 32 * k;
        const float bpv = bp[g];
        float* o = out + (size_t)(nb * FF + g) * TT + t0;
        #pragma unroll
        for (int p = 0; p < 4; p++) {
            float a, bv; unpack2(acc[k][p], a, bv);
            ((float2*)o)[p] = make_float2(a + bpv, bv + bpv);
        }
    }
}

// ======================== launch ==========================================
extern "C" void kernel_launch(void* const* d_in, const int* in_sizes, int n_in,
                              void* d_out, int out_size)
{
    (void)in_sizes; (void)n_in; (void)out_size;
    const float* x  = (const float*)d_in[0];
    const float* Wq = (const float*)d_in[1];
    const float* Wk = (const float*)d_in[2];
    const float* Wv = (const float*)d_in[3];
    const float* Wp = (const float*)d_in[4];
    const float* bp = (const float*)d_in[5];
    float* out = (float*)d_out;

    qkv_kernel<<<768, 256>>>(x, Wq, Wk, Wv);
    attn_kernel<<<2048, 256>>>();
    proj_kernel<<<256, 256>>>(Wp, bp, out);
}

// round 6
// speedup vs baseline: 2.3435x; 2.3435x over previous
#include <cuda_runtime.h>
#include <cuda_bf16.h>

#define NA 8
#define BB 32
#define NB 256
#define FF 256
#define TT 64
#define HH 8
#define DD 32
#define SCALE 0.0625f

typedef unsigned int u32;

// ---- packed (bf16 hi | bf16 lo<<16) intermediates ----
__device__ u32 g_w [3*FF*FF];      // [mat][fout=h*32+d][f]
__device__ u32 g_wp[FF*FF];        // [g][f]
__device__ u32 g_q [HH*NB*TT*DD];  // [h][nb][t][d]  (pre-scaled)
__device__ u32 g_k [HH*NB*TT*DD];  // [h][nb][s][d]
__device__ u32 g_v [HH*NB*DD*TT];  // [h][nb][d][s]
__device__ u32 g_y [NB*TT*FF];     // [nb][t][f]

__device__ __forceinline__ u32 splitpack(float x) {
    __nv_bfloat16 h = __float2bfloat16(x);
    __nv_bfloat16 l = __float2bfloat16(x - __bfloat162float(h));
    return (u32)__bfloat16_as_ushort(h) | ((u32)__bfloat16_as_ushort(l) << 16);
}
__device__ __forceinline__ u32 hi2(u32 a, u32 b) { return __byte_perm(a, b, 0x5410); }
__device__ __forceinline__ u32 lo2(u32 a, u32 b) { return __byte_perm(a, b, 0x7632); }

__device__ __forceinline__ void mma(float* c, u32 a0,u32 a1,u32 a2,u32 a3, u32 b0,u32 b1) {
    asm volatile("mma.sync.aligned.m16n8k16.row.col.f32.bf16.bf16.f32 "
        "{%0,%1,%2,%3},{%4,%5,%6,%7},{%8,%9},{%0,%1,%2,%3};"
        : "+f"(c[0]),"+f"(c[1]),"+f"(c[2]),"+f"(c[3])
        : "r"(a0),"r"(a1),"r"(a2),"r"(a3),"r"(b0),"r"(b1));
}
// xor-swizzled smem indices (conflict-free fragment loads, no padding)
__device__ __forceinline__ int sw16(int r, int w) { return r*16 + (w ^ ((r&6)<<1)); }
__device__ __forceinline__ int sw32(int r, int w) { return r*32 + (w ^ ((r&7)<<2)); }

// 3-term emulated-fp32 mma: hh + hl + lh
__device__ __forceinline__ void mma3(float* c, const u32* ah, const u32* al,
                                     u32 bh0, u32 bh1, u32 bl0, u32 bl1) {
    mma(c, ah[0],ah[1],ah[2],ah[3], bh0,bh1);
    mma(c, ah[0],ah[1],ah[2],ah[3], bl0,bl1);
    mma(c, al[0],al[1],al[2],al[3], bh0,bh1);
}

// ==================== kernel 0: split weights ====================
__global__ void __launch_bounds__(256) split_w(
    const float* __restrict__ Wq, const float* __restrict__ Wk,
    const float* __restrict__ Wv, const float* __restrict__ Wp)
{
    int t = blockIdx.x*256 + threadIdx.x;          // 65536
    int fo = t >> 8, f = t & 255;
    int src = ((fo>>5)*FF + f)*DD + (fo&31);       // W[h][f][d]
    g_w[t]          = splitpack(Wq[src]);
    g_w[65536 + t]  = splitpack(Wk[src]);
    g_w[131072 + t] = splitpack(Wv[src]);
    g_wp[t] = splitpack(Wp[t]);
}

// ==================== kernel 1: QKV ====================
// C[fout=256][t=64] = W^T x.  grid 768 = mat*256+nb, block 256 (8 warps: warp=head).
__global__ void __launch_bounds__(256) qkv_kernel(const float* __restrict__ x)
{
    __shared__ u32 Ah[256*16], Al[256*16];   // W rows (fout) x 16 f-pair words
    __shared__ u32 Bh[64*16],  Bl[64*16];    // x^T rows (t)  x 16 f-pair words

    const int bid = blockIdx.x, nb = bid & 255, mat = bid >> 8;
    const int tid = threadIdx.x, wid = tid >> 5, lane = tid & 31;
    const u32* Wm = g_w + mat*65536;
    const float* xb = x + nb*(FF*TT);

    float acc[2][8][4];
    #pragma unroll
    for (int mt=0;mt<2;mt++) for (int nt=0;nt<8;nt++) for (int p=0;p<4;p++) acc[mt][nt][p]=0.f;

    for (int c = 0; c < 8; c++) {
        __syncthreads();
        #pragma unroll
        for (int m = 0; m < 8; m++) {        // stage A: 2048 uint4
            int jj = tid + m*256, r = jj>>3, q = jj&7;
            uint4 p = *((const uint4*)(Wm + r*256 + c*32) + q);
            *(uint2*)&Ah[sw16(r,2*q)] = make_uint2(hi2(p.x,p.y), hi2(p.z,p.w));
            *(uint2*)&Al[sw16(r,2*q)] = make_uint2(lo2(p.x,p.y), lo2(p.z,p.w));
        }
        {   // stage B: transpose+split x; thread: t=tid>>2, 8 f's
            int t = tid>>2, q = tid&3;
            u32 sp[8];
            #pragma unroll
            for (int i = 0; i < 8; i++)
                sp[i] = splitpack(xb[(c*32 + q*8 + i)*TT + t]);
            #pragma unroll
            for (int i = 0; i < 4; i++) {
                Bh[sw16(t, q*4+i)] = hi2(sp[2*i], sp[2*i+1]);
                Bl[sw16(t, q*4+i)] = lo2(sp[2*i], sp[2*i+1]);
            }
        }
        __syncthreads();

        #pragma unroll
        for (int kt = 0; kt < 2; kt++) {
            const int wq = kt*8 + (lane&3);
            u32 ah[2][4], al[2][4];
            #pragma unroll
            for (int mt = 0; mt < 2; mt++) {
                int r = wid*32 + mt*16 + (lane>>2);
                ah[mt][0]=Ah[sw16(r,wq)];   ah[mt][1]=Ah[sw16(r+8,wq)];
                ah[mt][2]=Ah[sw16(r,wq+4)]; ah[mt][3]=Ah[sw16(r+8,wq+4)];
                al[mt][0]=Al[sw16(r,wq)];   al[mt][1]=Al[sw16(r+8,wq)];
                al[mt][2]=Al[sw16(r,wq+4)]; al[mt][3]=Al[sw16(r+8,wq+4)];
            }
            #pragma unroll
            for (int nt = 0; nt < 8; nt++) {
                int rb = nt*8 + (lane>>2);
                u32 bh0=Bh[sw16(rb,wq)], bh1=Bh[sw16(rb,wq+4)];
                u32 bl0=Bl[sw16(rb,wq)], bl1=Bl[sw16(rb,wq+4)];
                mma3(acc[0][nt], ah[0], al[0], bh0,bh1,bl0,bl1);
                mma3(acc[1][nt], ah[1], al[1], bh0,bh1,bl0,bl1);
            }
        }
    }

    // epilogue: warp = head
    const float sc = (mat == 0) ? SCALE : 1.0f;
    if (mat < 2) {
        u32* dst = (mat ? g_k : g_q) + (wid*NB + nb)*(TT*DD);
        #pragma unroll
        for (int mt = 0; mt < 2; mt++) {
            int d = mt*16 + (lane>>2);
            #pragma unroll
            for (int nt = 0; nt < 8; nt++) {
                int t = nt*8 + 2*(lane&3);
                dst[t*32 + d]         = splitpack(acc[mt][nt][0]*sc);
                dst[(t+1)*32 + d]     = splitpack(acc[mt][nt][1]*sc);
                dst[t*32 + d + 8]     = splitpack(acc[mt][nt][2]*sc);
                dst[(t+1)*32 + d + 8] = splitpack(acc[mt][nt][3]*sc);
            }
        }
    } else {
        u32* dst = g_v + (wid*NB + nb)*(TT*DD);   // [d][s]
        #pragma unroll
        for (int mt = 0; mt < 2; mt++) {
            int d = mt*16 + (lane>>2);
            #pragma unroll
            for (int nt = 0; nt < 8; nt++) {
                int s = nt*8 + 2*(lane&3);
                *(uint2*)&dst[d*64 + s] =
                    make_uint2(splitpack(acc[mt][nt][0]), splitpack(acc[mt][nt][1]));
                *(uint2*)&dst[(d+8)*64 + s] =
                    make_uint2(splitpack(acc[mt][nt][2]), splitpack(acc[mt][nt][3]));
            }
        }
    }
}

// ==================== kernel 2: attention ====================
// grid 2048 = h*256 + j*32 + b, block 128 (warp = 16-row t-strip).
__global__ void __launch_bounds__(128) attn_kernel()
{
    __shared__ u32 Qh[64*16], Ql[64*16];
    __shared__ u32 Kh[64*16], Kl[64*16];
    __shared__ u32 Vh[32*32], Vl[32*32];

    const int bid = blockIdx.x;
    const int b = bid & 31, j = (bid >> 5) & 7, h = bid >> 8;
    const int tid = threadIdx.x, wid = tid >> 5, lane = tid & 31;

    {   // stage Q once
        const uint4* qg = (const uint4*)(g_q + (h*NB + j*BB + b)*(TT*DD));
        #pragma unroll
        for (int m = 0; m < 4; m++) {
            int jj = tid + m*128, r = jj>>3, q = jj&7;
            uint4 p = qg[jj];
            *(uint2*)&Qh[sw16(r,2*q)] = make_uint2(hi2(p.x,p.y), hi2(p.z,p.w));
            *(uint2*)&Ql[sw16(r,2*q)] = make_uint2(lo2(p.x,p.y), lo2(p.z,p.w));
        }
    }

    float o[4][4];
    #pragma unroll
    for (int n=0;n<4;n++) for (int p=0;p<4;p++) o[n][p]=0.f;

    for (int i = 0; i < NA; i++) {
        __syncthreads();
        {   // stage K (s x d) and V (d x s) for agent i
            const uint4* kg = (const uint4*)(g_k + (h*NB + i*BB + b)*(TT*DD));
            const uint4* vg = (const uint4*)(g_v + (h*NB + i*BB + b)*(TT*DD));
            #pragma unroll
            for (int m = 0; m < 4; m++) {
                int jj = tid + m*128;
                { int r = jj>>3, q = jj&7; uint4 p = kg[jj];
                  *(uint2*)&Kh[sw16(r,2*q)] = make_uint2(hi2(p.x,p.y), hi2(p.z,p.w));
                  *(uint2*)&Kl[sw16(r,2*q)] = make_uint2(lo2(p.x,p.y), lo2(p.z,p.w)); }
                { int r = jj>>4, q = jj&15; uint4 p = vg[jj];
                  *(uint2*)&Vh[sw32(r,2*q)] = make_uint2(hi2(p.x,p.y), hi2(p.z,p.w));
                  *(uint2*)&Vl[sw32(r,2*q)] = make_uint2(lo2(p.x,p.y), lo2(p.z,p.w)); }
            }
        }
        __syncthreads();

        // ---- S = Q K^T (t16 x s64) ----
        float s[8][4];
        #pragma unroll
        for (int n=0;n<8;n++) for (int p=0;p<4;p++) s[n][p]=0.f;

        u32 qh[2][4], ql[2][4];
        #pragma unroll
        for (int kt = 0; kt < 2; kt++) {
            int wq = kt*8 + (lane&3), r = wid*16 + (lane>>2);
            qh[kt][0]=Qh[sw16(r,wq)];   qh[kt][1]=Qh[sw16(r+8,wq)];
            qh[kt][2]=Qh[sw16(r,wq+4)]; qh[kt][3]=Qh[sw16(r+8,wq+4)];
            ql[kt][0]=Ql[sw16(r,wq)];   ql[kt][1]=Ql[sw16(r+8,wq)];
            ql[kt][2]=Ql[sw16(r,wq+4)]; ql[kt][3]=Ql[sw16(r+8,wq+4)];
        }
        #pragma unroll
        for (int nt = 0; nt < 8; nt++) {
            int rb = nt*8 + (lane>>2);
            #pragma unroll
            for (int kt = 0; kt < 2; kt++) {
                int wq = kt*8 + (lane&3);
                u32 bh0=Kh[sw16(rb,wq)], bh1=Kh[sw16(rb,wq+4)];
                u32 bl0=Kl[sw16(rb,wq)], bl1=Kl[sw16(rb,wq+4)];
                mma3(s[nt], qh[kt], ql[kt], bh0,bh1,bl0,bl1);
            }
        }

        // ---- softmax over s=64 (rows r0, r0+8) ----
        float m0 = s[0][0], m1 = s[0][2];
        #pragma unroll
        for (int nt = 0; nt < 8; nt++) {
            m0 = fmaxf(m0, fmaxf(s[nt][0], s[nt][1]));
            m1 = fmaxf(m1, fmaxf(s[nt][2], s[nt][3]));
        }
        m0 = fmaxf(m0, __shfl_xor_sync(~0u, m0, 1)); m0 = fmaxf(m0, __shfl_xor_sync(~0u, m0, 2));
        m1 = fmaxf(m1, __shfl_xor_sync(~0u, m1, 1)); m1 = fmaxf(m1, __shfl_xor_sync(~0u, m1, 2));
        float sum0 = 0.f, sum1 = 0.f;
        #pragma unroll
        for (int nt = 0; nt < 8; nt++) {
            s[nt][0] = __expf(s[nt][0]-m0); s[nt][1] = __expf(s[nt][1]-m0);
            s[nt][2] = __expf(s[nt][2]-m1); s[nt][3] = __expf(s[nt][3]-m1);
            sum0 += s[nt][0] + s[nt][1];
            sum1 += s[nt][2] + s[nt][3];
        }
        sum0 += __shfl_xor_sync(~0u, sum0, 1); sum0 += __shfl_xor_sync(~0u, sum0, 2);
        sum1 += __shfl_xor_sync(~0u, sum1, 1); sum1 += __shfl_xor_sync(~0u, sum1, 2);
        float inv0 = __frcp_rn(sum0), inv1 = __frcp_rn(sum1);

        // ---- O += P V : P stays in registers as A-fragments ----
        #pragma unroll
        for (int kt = 0; kt < 4; kt++) {
            u32 x0, x1, ph[4], pl[4];
            x0 = splitpack(s[2*kt][0]*inv0);   x1 = splitpack(s[2*kt][1]*inv0);
            ph[0] = hi2(x0,x1); pl[0] = lo2(x0,x1);
            x0 = splitpack(s[2*kt][2]*inv1);   x1 = splitpack(s[2*kt][3]*inv1);
            ph[1] = hi2(x0,x1); pl[1] = lo2(x0,x1);
            x0 = splitpack(s[2*kt+1][0]*inv0); x1 = splitpack(s[2*kt+1][1]*inv0);
            ph[2] = hi2(x0,x1); pl[2] = lo2(x0,x1);
            x0 = splitpack(s[2*kt+1][2]*inv1); x1 = splitpack(s[2*kt+1][3]*inv1);
            ph[3] = hi2(x0,x1); pl[3] = lo2(x0,x1);
            #pragma unroll
            for (int nt = 0; nt < 4; nt++) {
                int rb = nt*8 + (lane>>2), wq = kt*8 + (lane&3);
                u32 bh0=Vh[sw32(rb,wq)], bh1=Vh[sw32(rb,wq+4)];
                u32 bl0=Vl[sw32(rb,wq)], bl1=Vl[sw32(rb,wq+4)];
                mma3(o[nt], ph, pl, bh0,bh1,bl0,bl1);
            }
        }
    }

    // epilogue: y[nb][t][h*32+d]
    const int nb = j*BB + b;
    const int t0 = wid*16 + (lane>>2);
    u32* yb = g_y + nb*(TT*FF) + h*32;
    #pragma unroll
    for (int nt = 0; nt < 4; nt++) {
        int d = nt*8 + 2*(lane&3);
        *(uint2*)&yb[t0*256 + d]     = make_uint2(splitpack(o[nt][0]), splitpack(o[nt][1]));
        *(uint2*)&yb[(t0+8)*256 + d] = make_uint2(splitpack(o[nt][2]), splitpack(o[nt][3]));
    }
}

// ==================== kernel 3: projection ====================
// C[t=64][g=256] = y Wp^T + bp.  grid 256 (nb), block 256
// warp: mt = wid&3 (t-strip), nh = wid>>2 (g-half of 16 n-tiles).
__global__ void __launch_bounds__(256) proj_kernel(
    const float* __restrict__ bp, float* __restrict__ out)
{
    __shared__ u32 Ah[64*16],  Al[64*16];    // y rows (t)
    __shared__ u32 Bh[256*16], Bl[256*16];   // Wp rows (g)

    const int nb = blockIdx.x;
    const int tid = threadIdx.x, wid = tid >> 5, lane = tid & 31;
    const int mt = wid & 3, nh = wid >> 2;

    float acc[16][4];
    #pragma unroll
    for (int n=0;n<16;n++) for (int p=0;p<4;p++) acc[n][p]=0.f;

    for (int c = 0; c < 8; c++) {
        __syncthreads();
        #pragma unroll
        for (int m = 0; m < 2; m++) {    // stage A (y chunk)
            int jj = tid + m*256, r = jj>>3, q = jj&7;
            uint4 p = *((const uint4*)(g_y + nb*(TT*FF) + r*256 + c*32) + q);
            *(uint2*)&Ah[sw16(r,2*q)] = make_uint2(hi2(p.x,p.y), hi2(p.z,p.w));
            *(uint2*)&Al[sw16(r,2*q)] = make_uint2(lo2(p.x,p.y), lo2(p.z,p.w));
        }
        #pragma unroll
        for (int m = 0; m < 8; m++) {    // stage B (Wp chunk)
            int jj = tid + m*256, r = jj>>3, q = jj&7;
            uint4 p = *((const uint4*)(g_wp + r*256 + c*32) + q);
            *(uint2*)&Bh[sw16(r,2*q)] = make_uint2(hi2(p.x,p.y), hi2(p.z,p.w));
            *(uint2*)&Bl[sw16(r,2*q)] = make_uint2(lo2(p.x,p.y), lo2(p.z,p.w));
        }
        __syncthreads();

        #pragma unroll
        for (int kt = 0; kt < 2; kt++) {
            const int wq = kt*8 + (lane&3);
            int r = mt*16 + (lane>>2);
            u32 ah[4], al[4];
            ah[0]=Ah[sw16(r,wq)];   ah[1]=Ah[sw16(r+8,wq)];
            ah[2]=Ah[sw16(r,wq+4)]; ah[3]=Ah[sw16(r+8,wq+4)];
            al[0]=Al[sw16(r,wq)];   al[1]=Al[sw16(r+8,wq)];
            al[2]=Al[sw16(r,wq+4)]; al[3]=Al[sw16(r+8,wq+4)];
            #pragma unroll
            for (int nt = 0; nt < 16; nt++) {
                int rb = nh*128 + nt*8 + (lane>>2);
                u32 bh0=Bh[sw16(rb,wq)], bh1=Bh[sw16(rb,wq+4)];
                u32 bl0=Bl[sw16(rb,wq)], bl1=Bl[sw16(rb,wq+4)];
                mma3(acc[nt], ah, al, bh0,bh1,bl0,bl1);
            }
        }
    }

    // epilogue: out[nb][g][t] + bp[g]
    const int t = mt*16 + (lane>>2);
    float* ob = out + nb*(FF*TT);
    #pragma unroll
    for (int nt = 0; nt < 16; nt++) {
        int g = nh*128 + nt*8 + 2*(lane&3);
        float b0 = __ldg(bp + g), b1 = __ldg(bp + g + 1);
        ob[g*64 + t]         = acc[nt][0] + b0;
        ob[(g+1)*64 + t]     = acc[nt][1] + b1;
        ob[g*64 + t + 8]     = acc[nt][2] + b0;
        ob[(g+1)*64 + t + 8] = acc[nt][3] + b1;
    }
}

// ==================== launch ====================
extern "C" void kernel_launch(void* const* d_in, const int* in_sizes, int n_in,
                              void* d_out, int out_size)
{
    (void)in_sizes; (void)n_in; (void)out_size;
    const float* x  = (const float*)d_in[0];
    const float* Wq = (const float*)d_in[1];
    const float* Wk = (const float*)d_in[2];
    const float* Wv = (const float*)d_in[3];
    const float* Wp = (const float*)d_in[4];
    const float* bp = (const float*)d_in[5];
    float* out = (float*)d_out;

    split_w<<<256, 256>>>(Wq, Wk, Wv, Wp);
    qkv_kernel<<<768, 256>>>(x);
    attn_kernel<<<2048, 128>>>();
    proj_kernel<<<256, 256>>>(bp, out);
}